// round 11
// baseline (speedup 1.0000x reference)
#include <cuda_runtime.h>
#include <math.h>
#include <stdint.h>

// Problem constants
#define SIG_LEN   131072
#define NW        4
#define ROWS      256
#define T_OUT     131166
#define SPLIT     8
#define CHK       16384               // input samples owned per block
#define SS        2048                // input samples per scan step

typedef unsigned long long ull;

__device__ float g_filt[2][4][16];    // [lp/hp][wavelet][tap]

// ---------------------------------------------------------------------------
// Filter constraint (fp32), 512 threads: 128 taps x 4-way k-split + reduce.
// ---------------------------------------------------------------------------
__global__ void __launch_bounds__(512) constrain_kernel(
        const float* __restrict__ low, const float* __restrict__ high) {
    __shared__ float ctab[64];
    __shared__ float part[512];
    __shared__ float taps[128];
    const int tid = threadIdx.x;                 // 0..511
    if (tid < 64) ctab[tid] = cosf(2.0f * (float)M_PI * (float)tid / 64.0f);
    __syncthreads();

    const int combo = tid >> 2;                  // 0..127
    const int kq    = tid & 3;                   // k quarter
    const int bank  = combo >> 6;                // 0 = lp, 1 = hp
    const int n     = (combo >> 4) & 3;          // wavelet
    const int j     = combo & 15;                // output tap
    const float* src = bank ? high : low;

    const float target = ((float)n + 0.5f) / (float)NW * 0.5f + (bank ? 0.5f : 0.0f);
    const float inv_width = (float)NW;

    float w[33];
    #pragma unroll
    for (int f = 0; f <= 32; f++) {
        float d = ((float)f / 32.0f - target) * inv_width;
        w[f] = expf(-d * d);
    }

    float acc = 0.0f;
    #pragma unroll
    for (int kk = 0; kk < 4; kk++) {
        int k  = 4 * kq + kk;
        int dm = j - k + 64;
        float c = w[0];
        #pragma unroll
        for (int f = 1; f <= 31; f++)
            c = fmaf(2.0f * w[f], ctab[(dm * f) & 63], c);
        c = fmaf(w[32], ctab[(dm * 32) & 63], c);
        acc = fmaf(src[n * 16 + k], c, acc);
    }
    part[tid] = acc;
    __syncthreads();

    if (tid < 128) {
        float tv = ((part[4 * tid] + part[4 * tid + 1]) +
                    (part[4 * tid + 2] + part[4 * tid + 3])) * (1.0f / 64.0f);
        taps[tid] = tv;
    }
    __syncthreads();

    if (tid < 128) {
        const int base = tid & ~15;
        float ss = 0.0f;
        #pragma unroll
        for (int m = 0; m < 16; m++) { float v = taps[base + m]; ss = fmaf(v, v, ss); }
        float nrm = sqrtf(ss);
        if (nrm < 1e-12f) nrm = 1e-12f;
        g_filt[tid >> 6][(tid >> 4) & 3][tid & 15] =
            taps[tid] / nrm * 1.41421356237309515f;
    }
}

// ---------------------------------------------------------------------------
__device__ __forceinline__ ull fma2(ull a, ull b, ull c) {
    ull d;
    asm("fma.rn.f32x2 %0, %1, %2, %3;" : "=l"(d) : "l"(a), "l"(b), "l"(c));
    return d;
}
__device__ __forceinline__ float hsum2(ull a) {
    float2 v = *reinterpret_cast<float2*>(&a);
    return v.x + v.y;
}
// Skew (applied to s_in only): conflict-free for 32B-strided LDS.128
__device__ __forceinline__ int SKW(int i) { return i + ((i >> 5) << 2); }

// Shared-memory arena (floats). s_in0/1 SKEWED; s_l1, s_a2 LINEAR.
// Tail overlays linear L3/L4/L5 on the s_in region. s_a2 persists.
#define OFF_IN0 0      // skewed, 2320 floats (SKW(2063)=2319)
#define OFF_IN1 2320   // skewed, 2320 floats
#define OFF_L1  4640   // linear, 1040 floats: pos p holds l1 out q = p-15
#define OFF_A2  5680   // linear, 4656 floats
#define ARENA   10336
// tail overlay (linear, within [0, 4640))
#define OFF_L3  0      // 2208 floats
#define OFF_L4  2208   // 1120 floats
#define OFF_L5  3328   // 576 floats

// ---------------------------------------------------------------------------
// Staging into SKEWED s_in: s_in[SKW(i)] = x[pin-15+i], i in [0, 2064).
// ---------------------------------------------------------------------------
template<bool CHECK>
__device__ __forceinline__ void stage(uint32_t smb, const float* __restrict__ x,
                                      int off, int pin, int tid)
{
    #pragma unroll
    for (int c = 0; c < 9; c++) {
        int i = tid + 256 * c;
        if (c == 8 && tid >= 16) break;
        int gi = pin - 15 + i;
        uint32_t sa = smb + (uint32_t)(off + SKW(i)) * 4u;
        if (CHECK) {
            bool ok = (gi >= 0) && (gi < SIG_LEN);
            const float* gp = x + (ok ? gi : 0);
            int sz = ok ? 4 : 0;
            asm volatile("cp.async.ca.shared.global [%0], [%1], 4, %2;"
                         :: "r"(sa), "l"(gp), "r"(sz) : "memory");
        } else {
            const float* gp = x + gi;
            asm volatile("cp.async.ca.shared.global [%0], [%1], 4;"
                         :: "r"(sa), "l"(gp) : "memory");
        }
    }
}

// ---------------------------------------------------------------------------
// Level-1 pass, 4 outputs/thread at q0 = 4t+1 (q in [1,1024]).
// Reads skewed s_in: window for out q = floats [2q .. 2q+15] (local idx).
// Approx -> s_l1[15+q] via one STS.128 at 16+4t. MODE: 0=halo (det only
// q==1024), 1=interior (shfl-densified det float2 stores), 2=final masked.
// ---------------------------------------------------------------------------
template<int MODE>
__device__ __forceinline__ void l1_pass4(const float* __restrict__ sin,
                                         float* __restrict__ l1,
                                         float* __restrict__ det, int hi,
                                         const ull* fa, const ull* fd, int tid)
{
    const int q0 = 4 * tid + 1;
    ull P[12];
    #pragma unroll
    for (int c = 0; c < 6; c++) {
        int idx = 8 * tid + 4 * c;
        ulonglong2 v = *(const ulonglong2*)(sin + SKW(idx));
        P[2 * c] = v.x; P[2 * c + 1] = v.y;
    }
    // Approx: out[q0+o] = hsum( sum_m fa[m] (*) P[o+1+m] )
    ull aa[4] = {0ull, 0ull, 0ull, 0ull};
    #pragma unroll
    for (int m = 0; m < 8; m++) {
        #pragma unroll
        for (int o = 0; o < 4; o++) aa[o] = fma2(fa[m], P[o + 1 + m], aa[o]);
    }
    float4 ra;
    ra.x = hsum2(aa[0]); ra.y = hsum2(aa[1]);
    ra.z = hsum2(aa[2]); ra.w = hsum2(aa[3]);
    *reinterpret_cast<float4*>(l1 + 16 + 4 * tid) = ra;

    // Detail (halo step: only warp 7 computes, only tid 255 stores q=1024)
    if (MODE != 0 || (tid >> 5) == 7) {
        ull dd[4] = {0ull, 0ull, 0ull, 0ull};
        #pragma unroll
        for (int m = 0; m < 8; m++) {
            #pragma unroll
            for (int o = 0; o < 4; o++) dd[o] = fma2(fd[m], P[o + 1 + m], dd[o]);
        }
        float rd0 = hsum2(dd[0]), rd1 = hsum2(dd[1]);
        float rd2 = hsum2(dd[2]), rd3 = hsum2(dd[3]);
        if (MODE == 0) {
            if (tid == 255) det[1024] = rd3;
        } else if (MODE == 1) {
            float rp = __shfl_up_sync(0xffffffffu, rd3, 1);
            int lane = tid & 31;
            if (lane == 0) {
                det[q0] = rd0;
            } else {
                *reinterpret_cast<float2*>(det + q0 - 1) = make_float2(rp, rd0);
            }
            *reinterpret_cast<float2*>(det + q0 + 1) = make_float2(rd1, rd2);
            if (lane == 31) det[q0 + 3] = rd3;
        } else {
            if (q0 < hi)     det[q0]     = rd0;
            if (q0 + 1 < hi) det[q0 + 1] = rd1;
            if (q0 + 2 < hi) det[q0 + 2] = rd2;
            if (q0 + 3 < hi) det[q0 + 3] = rd3;
        }
    }
}

// ---------------------------------------------------------------------------
// Level-2 pass (unchanged from R10): 512 outputs, 2/thread, linear s_l1.
// ---------------------------------------------------------------------------
template<bool DET, bool MASK>
__device__ __forceinline__ void l2_pass(const float* __restrict__ src,
                                        float* __restrict__ a2,
                                        float* __restrict__ det,
                                        int hi, int dqlim,
                                        const ull* fa, const ull* fd, int tid)
{
    const int q = 2 * tid;
    const float* w = src + 2 * q;
    ulonglong2 v0 = *(const ulonglong2*)(w);
    ulonglong2 v1 = *(const ulonglong2*)(w + 4);
    ulonglong2 v2 = *(const ulonglong2*)(w + 8);
    ulonglong2 v3 = *(const ulonglong2*)(w + 12);
    ull p8 = *(const ull*)(w + 16);
    ull P[9] = {v0.x, v0.y, v1.x, v1.y, v2.x, v2.y, v3.x, v3.y, p8};
    ull a0 = 0ull, a1 = 0ull;
    #pragma unroll
    for (int m = 0; m < 8; m++) {
        a0 = fma2(fa[m], P[m],     a0);
        a1 = fma2(fa[m], P[m + 1], a1);
    }
    float ra0 = hsum2(a0), ra1 = hsum2(a1);
    if (!MASK) { a2[q] = ra0; a2[q + 1] = ra1; }
    else {
        if (q < dqlim)     a2[q]     = ra0;
        if (q + 1 < dqlim) a2[q + 1] = ra1;
    }
    if (DET) {
        ull d0 = 0ull, d1 = 0ull;
        #pragma unroll
        for (int m = 0; m < 8; m++) {
            d0 = fma2(fd[m], P[m],     d0);
            d1 = fma2(fd[m], P[m + 1], d1);
        }
        float rd0 = hsum2(d0), rd1 = hsum2(d1);
        if (!MASK) {
            *reinterpret_cast<float2*>(det + q) = make_float2(rd0, rd1);
        } else {
            if (q < hi)     det[q]     = rd0;
            if (q + 1 < hi) det[q + 1] = rd1;
        }
    }
}

// ---------------------------------------------------------------------------
// Fused 6-level DWT. Grid (SPLIT, ROWS), 256 threads, 4 blocks/SM.
// ---------------------------------------------------------------------------
__global__ void __launch_bounds__(256, 4)
fused_dwt_kernel(const float* __restrict__ signal, float* __restrict__ out)
{
    __shared__ __align__(16) float sm[ARENA];
    const int tid = threadIdx.x;
    const int j   = blockIdx.x;
    const int r   = blockIdx.y;
    const int n   = r & 3;
    const float* x = signal + (size_t)(r >> 2) * SIG_LEN;
    float* orow = out + (size_t)r * T_OUT;

    uint32_t smb;
    asm("{ .reg .u64 t; cvta.to.shared.u64 t, %1; cvt.u32.u64 %0, t; }"
        : "=r"(smb) : "l"(sm));

    ull fa[8], fd[8];
    {
        const ull* fap = (const ull*)g_filt[0][n];
        const ull* fdp = (const ull*)g_filt[1][n];
        #pragma unroll
        for (int m = 0; m < 8; m++) { fa[m] = __ldg(fap + m); fd[m] = __ldg(fdp + m); }
    }

    // Init zeros: s_l1 carry source [1024..1039], s_a2 head pad + tail zeros
    if (tid < 16)               sm[OFF_L1 + 1024 + tid] = 0.f;
    if (tid >= 32 && tid < 35)  sm[OFF_A2 + (tid - 32)] = 0.f;
    if (tid >= 64 && tid < 112) sm[OFF_A2 + 4608 + (tid - 64)] = 0.f;

    const int Lout[6] = {65544, 32780, 16398, 8207, 4111, 2063};
    int olo[6], ohi[6];
    #pragma unroll
    for (int l = 0; l < 6; l++) {
        int c = CHK >> (l + 1);
        olo[l] = j * c;
        ohi[l] = (j == SPLIT - 1) ? Lout[l] : (j + 1) * c;
    }
    float* gd1 = orow + 65622;  float* gd2 = orow + 32842;
    float* gd3 = orow + 16444;  float* gd4 = orow + 8237;
    float* gd5 = orow + 4126;   float* gd6 = orow + 2063;

    // Generic masked 2-output level (tail levels 3..6)
    auto level = [&](const float* __restrict__ src, int woff,
                     float* __restrict__ dst, int dst0,
                     float* __restrict__ det, int tg0, int lo, int hi,
                     float* __restrict__ app, int nq)
    {
        for (int q = 2 * tid; q < nq; q += 512) {
            const float* w = src + woff + 2 * q;
            ulonglong2 v0 = *(const ulonglong2*)(w);
            ulonglong2 v1 = *(const ulonglong2*)(w + 4);
            ulonglong2 v2 = *(const ulonglong2*)(w + 8);
            ulonglong2 v3 = *(const ulonglong2*)(w + 12);
            ull p8 = *(const ull*)(w + 16);
            ull P[9] = {v0.x, v0.y, v1.x, v1.y, v2.x, v2.y, v3.x, v3.y, p8};
            ull a0 = 0ull, a1 = 0ull, d0 = 0ull, d1 = 0ull;
            #pragma unroll
            for (int m = 0; m < 8; m++) {
                a0 = fma2(fa[m], P[m],     a0);
                d0 = fma2(fd[m], P[m],     d0);
                a1 = fma2(fa[m], P[m + 1], a1);
                d1 = fma2(fd[m], P[m + 1], d1);
            }
            float ra0 = hsum2(a0), ra1 = hsum2(a1);
            float rd0 = hsum2(d0), rd1 = hsum2(d1);
            if (dst) { dst[dst0 + q] = ra0; dst[dst0 + q + 1] = ra1; }
            const int t = tg0 + q;
            if (t >= lo && t < hi)     { det[t]     = rd0; if (app) app[t]     = ra0; }
            if (t+1 >= lo && t+1 < hi) { det[t + 1] = rd1; if (app) app[t + 1] = ra1; }
        }
    };

    const int base2 = j * 4096 - 512;
    const int P0    = j * CHK - SS;
    const int nstep = (j == SPLIT - 1) ? 10 : 9;

    // Prologue staging (step 0 buffer)
    if (P0 >= 2048) stage<false>(smb, x, OFF_IN0, P0, tid);
    else            stage<true >(smb, x, OFF_IN0, P0, tid);
    asm volatile("cp.async.commit_group;" ::: "memory");

    for (int step = 0; step < nstep; step++) {
        const int pin  = P0 + step * SS;
        const int cbuf = (step & 1) ? OFF_IN1 : OFF_IN0;
        const int nbuf = (step & 1) ? OFF_IN0 : OFF_IN1;
        __syncthreads();                         // prev L1/L2 reads done

        // Carry s_l1 head (16 floats) <- old tail; prefetch; wait current.
        if (tid < 16) sm[OFF_L1 + tid] = sm[OFF_L1 + 1024 + tid];
        if (step + 1 < nstep) {
            const int np = pin + SS;
            if (np >= 2048 && np < 129024) stage<false>(smb, x, nbuf, np, tid);
            else                           stage<true >(smb, x, nbuf, np, tid);
            asm volatile("cp.async.commit_group;" ::: "memory");
            asm volatile("cp.async.wait_group 1;" ::: "memory");
        } else {
            asm volatile("cp.async.wait_group 0;" ::: "memory");
        }
        __syncthreads();

        // Level 1: q = 1..1024, t = (pin>>1)+q; approx -> s_l1[15+q]
        float* d1p = gd1 + (pin >> 1);
        if (step == 0)
            l1_pass4<0>(sm + cbuf, sm + OFF_L1, d1p, 0, fa, fd, tid);
        else if (step <= 8)
            l1_pass4<1>(sm + cbuf, sm + OFF_L1, d1p, 0, fa, fd, tid);
        else
            l1_pass4<2>(sm + cbuf, sm + OFF_L1, d1p,
                        ohi[0] - (pin >> 1), fa, fd, tid);
        __syncthreads();

        // Level 2: 512 outputs at t = (pin>>2)+q; approx -> s_a2[step*512+3+q]
        float* a2d = sm + OFF_A2 + step * 512 + 3;
        float* d2p = gd2 + (pin >> 2);
        if (step == 0)
            l2_pass<false, false>(sm + OFF_L1, a2d, d2p, 0, 0, fa, fd, tid);
        else if (step <= 8)
            l2_pass<true,  false>(sm + OFF_L1, a2d, d2p, 0, 0, fa, fd, tid);
        else
            l2_pass<true,  true >(sm + OFF_L1, a2d, d2p,
                                  ohi[1] - (pin >> 2),
                                  Lout[1] - (base2 + step * 512), fa, fd, tid);
    }

    __syncthreads();
    // Zero tail-buffer pads (heads [0,3) and right-edge zero regions)
    if (tid < 3) { sm[OFF_L3 + tid] = 0.f; sm[OFF_L4 + tid] = 0.f; sm[OFF_L5 + tid] = 0.f; }
    if (tid >= 32 && tid < 63)  sm[OFF_L3 + 2177 + (tid - 32)] = 0.f;
    if (tid >= 64 && tid < 94)  sm[OFF_L4 + 1090 + (tid - 64)] = 0.f;
    if (tid >= 96 && tid < 126) sm[OFF_L5 +  546 + (tid - 96)] = 0.f;
    __syncthreads();

    // Tail: levels 3..6 once. Left halos 112/48/16 cover the dependency cone.
    {
        const int a3 = olo[2] - 112, n3 = ohi[2] - a3;      // even
        level(sm + OFF_A2, 276, sm + OFF_L3, 3,
              gd3, a3, olo[2], ohi[2], (float*)0, n3);
        __syncthreads();

        const int a4 = olo[3] - 48, n4 = ohi[3] - a4;
        level(sm + OFF_L3, 4, sm + OFF_L4, 3,
              gd4, a4, olo[3], ohi[3], (float*)0, n4);
        __syncthreads();

        const int a5 = olo[4] - 16, n5 = ohi[4] - a5;
        level(sm + OFF_L4, 4, sm + OFF_L5, 3,
              gd5, a5, olo[4], ohi[4], (float*)0, n5);
        __syncthreads();

        level(sm + OFF_L5, 4, (float*)0, 0,
              gd6, olo[5], olo[5], ohi[5], orow, ohi[5] - olo[5]);
    }
}

// ---------------------------------------------------------------------------
extern "C" void kernel_launch(void* const* d_in, const int* in_sizes, int n_in,
                              void* d_out, int out_size) {
    const float* signal = (const float*)d_in[0];
    const float* low    = (const float*)d_in[1];
    const float* high   = (const float*)d_in[2];
    float* out = (float*)d_out;

    constrain_kernel<<<1, 512>>>(low, high);

    dim3 grid(SPLIT, ROWS);
    fused_dwt_kernel<<<grid, 256>>>(signal, out);
}

// round 12
// speedup vs baseline: 1.0718x; 1.0718x over previous
#include <cuda_runtime.h>
#include <math.h>
#include <stdint.h>

// Problem constants
#define SIG_LEN   131072
#define NW        4
#define ROWS      256
#define T_OUT     131166
#define SPLIT     8
#define CHK       16384               // input samples owned per block
#define SS        2048                // input samples per scan step

typedef unsigned long long ull;

__device__ float g_filt[2][4][16];    // [lp/hp][wavelet][tap]

// ---------------------------------------------------------------------------
// Filter constraint (fp32), 512 threads: 128 taps x 4-way k-split + reduce.
// ---------------------------------------------------------------------------
__global__ void __launch_bounds__(512) constrain_kernel(
        const float* __restrict__ low, const float* __restrict__ high) {
    __shared__ float ctab[64];
    __shared__ float part[512];
    __shared__ float taps[128];
    const int tid = threadIdx.x;                 // 0..511
    if (tid < 64) ctab[tid] = cosf(2.0f * (float)M_PI * (float)tid / 64.0f);
    __syncthreads();

    const int combo = tid >> 2;                  // 0..127
    const int kq    = tid & 3;                   // k quarter
    const int bank  = combo >> 6;                // 0 = lp, 1 = hp
    const int n     = (combo >> 4) & 3;          // wavelet
    const int j     = combo & 15;                // output tap
    const float* src = bank ? high : low;

    const float target = ((float)n + 0.5f) / (float)NW * 0.5f + (bank ? 0.5f : 0.0f);
    const float inv_width = (float)NW;

    float w[33];
    #pragma unroll
    for (int f = 0; f <= 32; f++) {
        float d = ((float)f / 32.0f - target) * inv_width;
        w[f] = expf(-d * d);
    }

    float acc = 0.0f;
    #pragma unroll
    for (int kk = 0; kk < 4; kk++) {
        int k  = 4 * kq + kk;
        int dm = j - k + 64;
        float c = w[0];
        #pragma unroll
        for (int f = 1; f <= 31; f++)
            c = fmaf(2.0f * w[f], ctab[(dm * f) & 63], c);
        c = fmaf(w[32], ctab[(dm * 32) & 63], c);
        acc = fmaf(src[n * 16 + k], c, acc);
    }
    part[tid] = acc;
    __syncthreads();

    if (tid < 128) {
        float tv = ((part[4 * tid] + part[4 * tid + 1]) +
                    (part[4 * tid + 2] + part[4 * tid + 3])) * (1.0f / 64.0f);
        taps[tid] = tv;
    }
    __syncthreads();

    if (tid < 128) {
        const int base = tid & ~15;
        float ss = 0.0f;
        #pragma unroll
        for (int m = 0; m < 16; m++) { float v = taps[base + m]; ss = fmaf(v, v, ss); }
        float nrm = sqrtf(ss);
        if (nrm < 1e-12f) nrm = 1e-12f;
        g_filt[tid >> 6][(tid >> 4) & 3][tid & 15] =
            taps[tid] / nrm * 1.41421356237309515f;
    }
}

// ---------------------------------------------------------------------------
__device__ __forceinline__ ull fma2(ull a, ull b, ull c) {
    ull d;
    asm("fma.rn.f32x2 %0, %1, %2, %3;" : "=l"(d) : "l"(a), "l"(b), "l"(c));
    return d;
}
__device__ __forceinline__ float hsum2(ull a) {
    float2 v = *reinterpret_cast<float2*>(&a);
    return v.x + v.y;
}

// Shared-memory arena (floats, DYNAMIC). Triple-buffered s_in and s_l1,
// persistent s_a2. Tail overlays linear L3/L4/L5 on the s_in region.
#define IN_SZ   2064   // staged window floats per buffer
#define L1_SZ   1040   // 15 head + 1024 outputs + 1 pad
#define OFF_L1B (3 * IN_SZ)            // 6192
#define OFF_A2  (OFF_L1B + 3 * L1_SZ)  // 9312
#define ARENA   (OFF_A2 + 4656)        // 13968 floats = 55872 B
// tail overlay (within s_in region [0, 6192))
#define OFF_L3  0      // 2208 floats
#define OFF_L4  2208   // 1120 floats
#define OFF_L5  3328   // 576 floats

// ---------------------------------------------------------------------------
// Staging: s_in[i] = x[pin-15+i], i in [0, 2064). CHECK=false -> bare cp.async.
// ---------------------------------------------------------------------------
template<bool CHECK>
__device__ __forceinline__ void stage(uint32_t smb, const float* __restrict__ x,
                                      int off, int pin, int tid)
{
    #pragma unroll
    for (int c = 0; c < 9; c++) {
        int i = tid + 256 * c;
        if (c == 8 && tid >= 16) break;
        int gi = pin - 15 + i;
        uint32_t sa = smb + (uint32_t)(off + i) * 4u;
        if (CHECK) {
            bool ok = (gi >= 0) && (gi < SIG_LEN);
            const float* gp = x + (ok ? gi : 0);
            int sz = ok ? 4 : 0;
            asm volatile("cp.async.ca.shared.global [%0], [%1], 4, %2;"
                         :: "r"(sa), "l"(gp), "r"(sz) : "memory");
        } else {
            const float* gp = x + gi;
            asm volatile("cp.async.ca.shared.global [%0], [%1], 4;"
                         :: "r"(sa), "l"(gp) : "memory");
        }
    }
}

// ---------------------------------------------------------------------------
// Level-1 pass: 1024 outputs, 2/thread x 2 iters. Window q = src[2q..2q+17].
// Approx -> dst[15+q]; outputs 1009..1023 echoed into nxt[0..14] (next
// rotation buffer's head carry). Detail -> det[q].
// ---------------------------------------------------------------------------
template<bool DET, bool MASK>
__device__ __forceinline__ void l1_pass(const float* __restrict__ src,
                                        float* __restrict__ dst,
                                        float* __restrict__ nxt,
                                        float* __restrict__ det, int hi,
                                        const ull* fa, const ull* fd, int tid)
{
    #pragma unroll
    for (int it = 0; it < 2; it++) {
        const int q = 2 * tid + 512 * it;
        const float* w = src + 2 * q;
        ulonglong2 v0 = *(const ulonglong2*)(w);
        ulonglong2 v1 = *(const ulonglong2*)(w + 4);
        ulonglong2 v2 = *(const ulonglong2*)(w + 8);
        ulonglong2 v3 = *(const ulonglong2*)(w + 12);
        ull p8 = *(const ull*)(w + 16);
        ull P[9] = {v0.x, v0.y, v1.x, v1.y, v2.x, v2.y, v3.x, v3.y, p8};
        ull a0 = 0ull, a1 = 0ull;
        #pragma unroll
        for (int m = 0; m < 8; m++) {
            a0 = fma2(fa[m], P[m],     a0);
            a1 = fma2(fa[m], P[m + 1], a1);
        }
        float ra0 = hsum2(a0), ra1 = hsum2(a1);
        dst[15 + q] = ra0;
        dst[16 + q] = ra1;
        if (it == 1) {                           // echo tail into next head
            if (q >= 1009)     nxt[q - 1009] = ra0;
            if (q + 1 >= 1009) nxt[q - 1008] = ra1;
        }
        if (DET) {
            ull d0 = 0ull, d1 = 0ull;
            #pragma unroll
            for (int m = 0; m < 8; m++) {
                d0 = fma2(fd[m], P[m],     d0);
                d1 = fma2(fd[m], P[m + 1], d1);
            }
            float rd0 = hsum2(d0), rd1 = hsum2(d1);
            if (!MASK) {
                *reinterpret_cast<float2*>(det + q) = make_float2(rd0, rd1);
            } else {
                if (q < hi)     det[q]     = rd0;
                if (q + 1 < hi) det[q + 1] = rd1;
            }
        }
    }
}

// ---------------------------------------------------------------------------
// Level-2 pass: 512 outputs, 2/thread. Window q = src[2q..2q+17].
// ---------------------------------------------------------------------------
template<bool DET, bool MASK>
__device__ __forceinline__ void l2_pass(const float* __restrict__ src,
                                        float* __restrict__ a2,
                                        float* __restrict__ det,
                                        int hi, int dqlim,
                                        const ull* fa, const ull* fd, int tid)
{
    const int q = 2 * tid;
    const float* w = src + 2 * q;
    ulonglong2 v0 = *(const ulonglong2*)(w);
    ulonglong2 v1 = *(const ulonglong2*)(w + 4);
    ulonglong2 v2 = *(const ulonglong2*)(w + 8);
    ulonglong2 v3 = *(const ulonglong2*)(w + 12);
    ull p8 = *(const ull*)(w + 16);
    ull P[9] = {v0.x, v0.y, v1.x, v1.y, v2.x, v2.y, v3.x, v3.y, p8};
    ull a0 = 0ull, a1 = 0ull;
    #pragma unroll
    for (int m = 0; m < 8; m++) {
        a0 = fma2(fa[m], P[m],     a0);
        a1 = fma2(fa[m], P[m + 1], a1);
    }
    float ra0 = hsum2(a0), ra1 = hsum2(a1);
    if (!MASK) { a2[q] = ra0; a2[q + 1] = ra1; }
    else {
        if (q < dqlim)     a2[q]     = ra0;
        if (q + 1 < dqlim) a2[q + 1] = ra1;
    }
    if (DET) {
        ull d0 = 0ull, d1 = 0ull;
        #pragma unroll
        for (int m = 0; m < 8; m++) {
            d0 = fma2(fd[m], P[m],     d0);
            d1 = fma2(fd[m], P[m + 1], d1);
        }
        float rd0 = hsum2(d0), rd1 = hsum2(d1);
        if (!MASK) {
            *reinterpret_cast<float2*>(det + q) = make_float2(rd0, rd1);
        } else {
            if (q < hi)     det[q]     = rd0;
            if (q + 1 < hi) det[q + 1] = rd1;
        }
    }
}

// ---------------------------------------------------------------------------
// Fused 6-level DWT. Grid (SPLIT, ROWS), 256 threads.
// Software-pipelined phases: phase k = { l1(step k) ; l2(step k-1) } on
// mod-3 rotating buffers; ONE __syncthreads per phase.
// ---------------------------------------------------------------------------
__global__ void __launch_bounds__(256, 4)
fused_dwt_kernel(const float* __restrict__ signal, float* __restrict__ out)
{
    extern __shared__ __align__(16) float sm[];
    const int tid = threadIdx.x;
    const int j   = blockIdx.x;
    const int r   = blockIdx.y;
    const int n   = r & 3;
    const float* x = signal + (size_t)(r >> 2) * SIG_LEN;
    float* orow = out + (size_t)r * T_OUT;

    uint32_t smb;
    asm("{ .reg .u64 t; cvta.to.shared.u64 t, %1; cvt.u32.u64 %0, t; }"
        : "=r"(smb) : "l"(sm));

    ull fa[8], fd[8];
    {
        const ull* fap = (const ull*)g_filt[0][n];
        const ull* fdp = (const ull*)g_filt[1][n];
        #pragma unroll
        for (int m = 0; m < 8; m++) { fa[m] = __ldg(fap + m); fd[m] = __ldg(fdp + m); }
    }

    // Init zeros: l1 buf0 head (zero-pad carry), s_a2 head pad + tail zeros
    if (tid < 15)               sm[OFF_L1B + tid] = 0.f;
    if (tid >= 32 && tid < 35)  sm[OFF_A2 + (tid - 32)] = 0.f;
    if (tid >= 64 && tid < 112) sm[OFF_A2 + 4608 + (tid - 64)] = 0.f;

    const int Lout[6] = {65544, 32780, 16398, 8207, 4111, 2063};
    int olo[6], ohi[6];
    #pragma unroll
    for (int l = 0; l < 6; l++) {
        int c = CHK >> (l + 1);
        olo[l] = j * c;
        ohi[l] = (j == SPLIT - 1) ? Lout[l] : (j + 1) * c;
    }
    float* gd1 = orow + 65622;  float* gd2 = orow + 32842;
    float* gd3 = orow + 16444;  float* gd4 = orow + 8237;
    float* gd5 = orow + 4126;   float* gd6 = orow + 2063;

    // Generic masked 2-output level (tail levels 3..6)
    auto level = [&](const float* __restrict__ src, int woff,
                     float* __restrict__ dst, int dst0,
                     float* __restrict__ det, int tg0, int lo, int hi,
                     float* __restrict__ app, int nq)
    {
        for (int q = 2 * tid; q < nq; q += 512) {
            const float* w = src + woff + 2 * q;
            ulonglong2 v0 = *(const ulonglong2*)(w);
            ulonglong2 v1 = *(const ulonglong2*)(w + 4);
            ulonglong2 v2 = *(const ulonglong2*)(w + 8);
            ulonglong2 v3 = *(const ulonglong2*)(w + 12);
            ull p8 = *(const ull*)(w + 16);
            ull P[9] = {v0.x, v0.y, v1.x, v1.y, v2.x, v2.y, v3.x, v3.y, p8};
            ull a0 = 0ull, a1 = 0ull, d0 = 0ull, d1 = 0ull;
            #pragma unroll
            for (int m = 0; m < 8; m++) {
                a0 = fma2(fa[m], P[m],     a0);
                d0 = fma2(fd[m], P[m],     d0);
                a1 = fma2(fa[m], P[m + 1], a1);
                d1 = fma2(fd[m], P[m + 1], d1);
            }
            float ra0 = hsum2(a0), ra1 = hsum2(a1);
            float rd0 = hsum2(d0), rd1 = hsum2(d1);
            if (dst) { dst[dst0 + q] = ra0; dst[dst0 + q + 1] = ra1; }
            const int t = tg0 + q;
            if (t >= lo && t < hi)     { det[t]     = rd0; if (app) app[t]     = ra0; }
            if (t+1 >= lo && t+1 < hi) { det[t + 1] = rd1; if (app) app[t + 1] = ra1; }
        }
    };

    const int base2 = j * 4096 - 512;
    const int P0    = j * CHK - SS;
    const int nstep = (j == SPLIT - 1) ? 10 : 9;

    // Prologue: stage step 0 into s_in buf 0
    if (P0 >= 2048) stage<false>(smb, x, 0, P0, tid);
    else            stage<true >(smb, x, 0, P0, tid);
    asm volatile("cp.async.commit_group;" ::: "memory");

    int mc = 0;                                  // ph % 3
    for (int ph = 0; ph <= nstep; ph++) {
        const int mn = (mc == 2) ? 0 : mc + 1;   // (ph+1) % 3
        // Prefetch staging for step ph+1 (buffer mn untouched this phase)
        if (ph + 1 < nstep) {
            const int np = P0 + (ph + 1) * SS;
            if (np >= 2048 && np < 129024) stage<false>(smb, x, mn * IN_SZ, np, tid);
            else                           stage<true >(smb, x, mn * IN_SZ, np, tid);
            asm volatile("cp.async.commit_group;" ::: "memory");
            asm volatile("cp.async.wait_group 1;" ::: "memory");
        } else {
            asm volatile("cp.async.wait_group 0;" ::: "memory");
        }
        __syncthreads();                         // single barrier per phase

        // Level 1 of step ph
        if (ph < nstep) {
            const int pin = P0 + ph * SS;
            const float* sin = sm + mc * IN_SZ;
            float* l1c = sm + OFF_L1B + mc * L1_SZ;
            float* l1n = sm + OFF_L1B + mn * L1_SZ;
            float* d1p = gd1 + (pin >> 1);
            if (ph == 0)
                l1_pass<false, false>(sin, l1c, l1n, d1p, 0, fa, fd, tid);
            else if (ph <= 8)
                l1_pass<true,  false>(sin, l1c, l1n, d1p, 0, fa, fd, tid);
            else
                l1_pass<true,  true >(sin, l1c, l1n, d1p,
                                      ohi[0] - (pin >> 1), fa, fd, tid);
        }
        // Level 2 of step ph-1
        if (ph >= 1) {
            const int s   = ph - 1;
            const int mp  = (mc == 0) ? 2 : mc - 1;      // s % 3
            const int pin = P0 + s * SS;
            const float* l1p = sm + OFF_L1B + mp * L1_SZ;
            float* a2d = sm + OFF_A2 + s * 512 + 3;
            float* d2p = gd2 + (pin >> 2);
            if (s == 0)
                l2_pass<false, false>(l1p, a2d, d2p, 0, 0, fa, fd, tid);
            else if (s <= 8)
                l2_pass<true,  false>(l1p, a2d, d2p, 0, 0, fa, fd, tid);
            else
                l2_pass<true,  true >(l1p, a2d, d2p,
                                      ohi[1] - (pin >> 2),
                                      Lout[1] - (base2 + s * 512), fa, fd, tid);
        }
        mc = mn;
    }

    __syncthreads();
    // Zero tail-buffer pads (heads [0,3) and right-edge zero regions)
    if (tid < 3) { sm[OFF_L3 + tid] = 0.f; sm[OFF_L4 + tid] = 0.f; sm[OFF_L5 + tid] = 0.f; }
    if (tid >= 32 && tid < 63)  sm[OFF_L3 + 2177 + (tid - 32)] = 0.f;
    if (tid >= 64 && tid < 94)  sm[OFF_L4 + 1090 + (tid - 64)] = 0.f;
    if (tid >= 96 && tid < 126) sm[OFF_L5 +  546 + (tid - 96)] = 0.f;
    __syncthreads();

    // Tail: levels 3..6 once. Left halos 112/48/16 cover the dependency cone.
    {
        const int a3 = olo[2] - 112, n3 = ohi[2] - a3;      // even
        level(sm + OFF_A2, 276, sm + OFF_L3, 3,
              gd3, a3, olo[2], ohi[2], (float*)0, n3);
        __syncthreads();

        const int a4 = olo[3] - 48, n4 = ohi[3] - a4;
        level(sm + OFF_L3, 4, sm + OFF_L4, 3,
              gd4, a4, olo[3], ohi[3], (float*)0, n4);
        __syncthreads();

        const int a5 = olo[4] - 16, n5 = ohi[4] - a5;
        level(sm + OFF_L4, 4, sm + OFF_L5, 3,
              gd5, a5, olo[4], ohi[4], (float*)0, n5);
        __syncthreads();

        level(sm + OFF_L5, 4, (float*)0, 0,
              gd6, olo[5], olo[5], ohi[5], orow, ohi[5] - olo[5]);
    }
}

// ---------------------------------------------------------------------------
extern "C" void kernel_launch(void* const* d_in, const int* in_sizes, int n_in,
                              void* d_out, int out_size) {
    const float* signal = (const float*)d_in[0];
    const float* low    = (const float*)d_in[1];
    const float* high   = (const float*)d_in[2];
    float* out = (float*)d_out;

    constrain_kernel<<<1, 512>>>(low, high);

    cudaFuncSetAttribute(fused_dwt_kernel,
                         cudaFuncAttributeMaxDynamicSharedMemorySize,
                         ARENA * (int)sizeof(float));
    dim3 grid(SPLIT, ROWS);
    fused_dwt_kernel<<<grid, 256, ARENA * sizeof(float)>>>(signal, out);
}